// round 17
// baseline (speedup 1.0000x reference)
#include <cuda_runtime.h>
#include <math.h>

#define H 512
#define W 512
#define NS 14            // number of gaussian scales (K+1)
#define NK 13            // number of DoG planes (K)
#define MAXR 43
#define NROWS (NK*H)
#define THRESH 0.001f
#define MAXPEAKS 32768
#define HW (H*W)

// ---- scratch (static device memory; no allocations allowed) ----
__device__ float  d_tmpf[NS*H*W];     // after horizontal blur (fp32-rounded)
// g pyramid with 1024-float guard pads on both sides so peak_k can read
// halo cells unclamped (garbage there only consumed as neighbors of
// border-excluded pixels -> never affects results).
__device__ __align__(16) float d_gbuf[NS*H*W + 2048];
#define D_G (d_gbuf + 1024)
__device__ float  d_kx[NS*96];        // 1D kernels, fp32-rounded coeffs (padded)
__device__ int    d_rad[NS];
__device__ float  d_sig[NS];
__device__ unsigned d_maskw[NROWS*16];// 512-bit peak mask per (k,y) row
                                      // (k=0 and k=12 rows: never written, BSS zero)
__device__ int    d_pcnt[NROWS*4];    // per-(row, x-block) popcounts (k=0/12: BSS zero)
__device__ int    d_rowcnt[NROWS];    // exclusive offsets after scan
__device__ int    d_total;            // total peak count

// Anchored Fast2Sum: hi >= 2 > b >= 0 always -> error extraction exact.
#define F2S(hi_, lo_, b_) do { \
    float t2_ = __fadd_rn(hi_, b_); \
    float u_  = __fsub_rn(t2_, hi_); \
    float e_  = __fsub_rn(b_, u_); \
    hi_ = t2_; \
    lo_ = __fadd_rn(lo_, e_); \
} while (0)

// ---------------------------------------------------------------
// Build normalized 1D gaussian kernels in fp64, round to fp32.
// ---------------------------------------------------------------
__global__ void build_kernels_k(const float* __restrict__ sigma_list) {
    int i   = blockIdx.x;
    int tid = threadIdx.x;      // 128 threads
    float sf = sigma_list[i];
    double s = (double)sf;
    int r   = (int)floor(4.0 * s + 0.5);   // TRUNCATE=4
    int n   = 2 * r + 1;
    __shared__ double tmp[96];
    __shared__ double ssum;
    if (tid < n) {
        double mean = 0.5 * (double)(n - 1);
        double d = ((double)tid - mean) / (2.0 * s);
        tmp[tid] = exp(-(d * d));
    }
    __syncthreads();
    if (tid == 0) {
        double acc = 0.0;
        for (int j = 0; j < n; j++) acc += tmp[j];
        ssum = acc;
        d_rad[i] = r;
        d_sig[i] = sf;
    }
    __syncthreads();
    if (tid < 96) d_kx[i*96 + tid] = (tid < n) ? (float)(tmp[tid] / ssum) : 0.f;
}

// ---------------------------------------------------------------
// Horizontal pass. Symmetric pairing (a_l+a_r)*k, TWO pairs folded
// per anchored Fast2Sum (K=2, validated). Unroll 4 -> slides become
// register renaming. 4 outputs/thread. blockDim 128, grid (H, NS).
// ---------------------------------------------------------------
__global__ void hblur_k(const float* __restrict__ x) {
    int y  = blockIdx.x;
    int sc = blockIdx.y;
    int r  = d_rad[sc];
    int n  = 2 * r + 1;
    __shared__ float srow[W + 2*MAXR + 8];
    __shared__ float sk[96];
    int tid = threadIdx.x;
    for (int i = tid; i < W + 2*r + 4; i += 128) {
        int xx = i - r;
        srow[i] = (xx >= 0 && xx < W) ? x[y*W + xx] : 0.f;
    }
    for (int i = tid; i < n; i += 128) sk[i] = d_kx[sc*96 + i];
    __syncthreads();

    int xo = tid * 4;
    float wl[5], wr[5];
    #pragma unroll
    for (int q = 0; q < 5; q++) {
        wl[q] = srow[xo + q];
        wr[q] = srow[xo + n - 2 + q];
    }
    float hi[4] = {2.f, 2.f, 2.f, 2.f};
    float lo[4] = {0.f, 0.f, 0.f, 0.f};

    int j = 0;
    #pragma unroll 4
    for (; j + 1 < r; j += 2) {
        float k0 = sk[j], k1 = sk[j+1];
        #pragma unroll
        for (int t = 0; t < 4; t++) {
            float s1 = __fadd_rn(wl[t],   wr[t+1]);
            float b  = __fmul_rn(s1, k0);
            float s2 = __fadd_rn(wl[t+1], wr[t]);
            b = __fmaf_rn(s2, k1, b);
            F2S(hi[t], lo[t], b);
        }
        wl[0] = wl[2]; wl[1] = wl[3]; wl[2] = wl[4];
        wl[3] = srow[xo + j + 5];
        wl[4] = srow[xo + j + 6];
        wr[4] = wr[2]; wr[3] = wr[1]; wr[2] = wr[0];
        wr[0] = srow[xo + n - 4 - j];
        wr[1] = srow[xo + n - 3 - j];
    }
    if (r & 1) {
        float kj = sk[r-1];
        float kc = sk[r];
        #pragma unroll
        for (int t = 0; t < 4; t++) {
            float s = __fadd_rn(wl[t], wr[t+1]);
            float b = __fmul_rn(s, kj);
            b = __fmaf_rn(wl[t+1], kc, b);
            F2S(hi[t], lo[t], b);
        }
    } else {
        float kc = sk[r];
        #pragma unroll
        for (int t = 0; t < 4; t++) {
            float b = __fmul_rn(wl[t], kc);
            F2S(hi[t], lo[t], b);
        }
    }
    float4 o;
    o.x = __fadd_rn(__fsub_rn(hi[0], 2.f), lo[0]);
    o.y = __fadd_rn(__fsub_rn(hi[1], 2.f), lo[1]);
    o.z = __fadd_rn(__fsub_rn(hi[2], 2.f), lo[2]);
    o.w = __fadd_rn(__fsub_rn(hi[3], 2.f), lo[3]);
    *(float4*)(d_tmpf + (size_t)(sc*H + y) * W + xo) = o;
}

// ---------------------------------------------------------------
// Vertical pass, K=2 block-compensated, VTY=64 tile, unroll 4.
// blockDim (32,16)=512, 4 outputs/thread, grid (16, 8, NS).
// ---------------------------------------------------------------
#define VTX 32
#define VTY 64
__global__ void vblur_k() {
    int sc = blockIdx.z;
    int x0 = blockIdx.x * VTX;
    int y0 = blockIdx.y * VTY;
    int r  = d_rad[sc];
    int n  = 2 * r + 1;
    __shared__ float tile[(VTY + 2*MAXR + 4) * VTX];   // 154*32*4 = 19.7KB
    __shared__ float sk[96];
    int tx  = threadIdx.x;
    int tid = tx + threadIdx.y * VTX;   // 512 threads
    int rows = VTY + 2 * r + 3;
    const float* inp = d_tmpf + (size_t)sc * HW;
    for (int i = tid; i < rows * VTX; i += 512) {
        int rr = i / VTX, cc = i % VTX;
        int gy = y0 - r + rr;
        tile[i] = (gy >= 0 && gy < H) ? inp[gy*W + x0 + cc] : 0.f;
    }
    for (int i = tid; i < n; i += 512) sk[i] = d_kx[sc*96 + i];
    __syncthreads();

    int yo = threadIdx.y * 4;
    float wl[5], wr[5];
    #pragma unroll
    for (int q = 0; q < 5; q++) {
        wl[q] = tile[(yo + q)*VTX + tx];
        wr[q] = tile[(yo + n - 2 + q)*VTX + tx];
    }
    float hi[4] = {2.f, 2.f, 2.f, 2.f};
    float lo[4] = {0.f, 0.f, 0.f, 0.f};

    int j = 0;
    #pragma unroll 4
    for (; j + 1 < r; j += 2) {
        float k0 = sk[j], k1 = sk[j+1];
        #pragma unroll
        for (int t = 0; t < 4; t++) {
            float s1 = __fadd_rn(wl[t],   wr[t+1]);
            float b  = __fmul_rn(s1, k0);
            float s2 = __fadd_rn(wl[t+1], wr[t]);
            b = __fmaf_rn(s2, k1, b);
            F2S(hi[t], lo[t], b);
        }
        wl[0] = wl[2]; wl[1] = wl[3]; wl[2] = wl[4];
        wl[3] = tile[(yo + j + 5)*VTX + tx];
        wl[4] = tile[(yo + j + 6)*VTX + tx];
        wr[4] = wr[2]; wr[3] = wr[1]; wr[2] = wr[0];
        wr[0] = tile[(yo + n - 4 - j)*VTX + tx];
        wr[1] = tile[(yo + n - 3 - j)*VTX + tx];
    }
    if (r & 1) {
        float kj = sk[r-1];
        float kc = sk[r];
        #pragma unroll
        for (int t = 0; t < 4; t++) {
            float s = __fadd_rn(wl[t], wr[t+1]);
            float b = __fmul_rn(s, kj);
            b = __fmaf_rn(wl[t+1], kc, b);
            F2S(hi[t], lo[t], b);
        }
    } else {
        float kc = sk[r];
        #pragma unroll
        for (int t = 0; t < 4; t++) {
            float b = __fmul_rn(wl[t], kc);
            F2S(hi[t], lo[t], b);
        }
    }
    float* outp = D_G + (size_t)sc * HW;
    #pragma unroll
    for (int t = 0; t < 4; t++)
        outp[(y0 + yo + t)*W + x0 + tx] =
            __fadd_rn(__fsub_rn(hi[t], 2.f), lo[t]);
}

// ---------------------------------------------------------------
// FUSED DoG + peak, TWO test planes per block (static k-pairing).
// Block loads g[kt0-1 .. kt0+ntest+1] once, computes ntest+2 dog
// tiles, then per test plane does the separable max + compare.
// pk = (c > THRESH) && (c >= max27) == reference semantics exactly.
// blockDim (32,8); grid (4, 64, 6): pairs (1,2)..(9,10), single (11).
// ---------------------------------------------------------------
#define PTX 128
#define PTY 8
#define TC2 136
#define NV 34
__global__ void peak_k() {
    int kt0   = 1 + blockIdx.z * 2;        // first test plane (1,3,5,7,9,11)
    int ntest = (kt0 < NK-2) ? 2 : 1;      // kt0=11 -> 1
    int ndog  = ntest + 2;                 // dog planes kt0-1 .. kt0+ntest
    int y0 = blockIdx.y * PTY;
    int x0 = blockIdx.x * PTX;
    __shared__ __align__(16) float dgs[4][PTY + 2][TC2];
    __shared__ float svmax[PTY][TC2];
    int tx = threadIdx.x;
    int ty = threadIdx.y;
    int tid = tx + ty * 32;             // 256 threads

    // fill: load ndog+1 g planes per cell, emit ndog dog tiles
    const float* gbase = D_G + (size_t)(kt0 - 1) * HW;
    for (int idx = tid; idx < (PTY + 2) * NV; idx += 256) {
        int rr = idx / NV, cc = idx - rr * NV;
        int gi = (y0 - 1 + rr) * W + (x0 - 4) + cc * 4;
        float4 gprev = *(const float4*)(gbase + gi);
        for (int p = 0; p < ndog; p++) {
            float4 gnext = *(const float4*)(gbase + (p+1)*HW + gi);
            float sg = d_sig[kt0 - 1 + p];
            float4 dg;
            dg.x = (gprev.x - gnext.x) * sg;
            dg.y = (gprev.y - gnext.y) * sg;
            dg.z = (gprev.z - gnext.z) * sg;
            dg.w = (gprev.w - gnext.w) * sg;
            *(float4*)&dgs[p][rr][cc*4] = dg;
            gprev = gnext;
        }
    }
    __syncthreads();

    int y = y0 + ty;
    bool yok = (y >= 1 && y <= H-2);
    for (int t = 0; t < ntest; t++) {
        int kt = kt0 + t;
        // fused z+vertical max: 3 dog planes (t..t+2) x 3 rows
        #pragma unroll
        for (int cc = tx; cc < TC2; cc += 32) {
            float m0 = fmaxf(fmaxf(dgs[t][ty  ][cc], dgs[t+1][ty  ][cc]), dgs[t+2][ty  ][cc]);
            float m1 = fmaxf(fmaxf(dgs[t][ty+1][cc], dgs[t+1][ty+1][cc]), dgs[t+2][ty+1][cc]);
            float m2 = fmaxf(fmaxf(dgs[t][ty+2][cc], dgs[t+1][ty+2][cc]), dgs[t+2][ty+2][cc]);
            svmax[ty][cc] = fmaxf(fmaxf(m0, m1), m2);
        }
        __syncwarp();   // svmax row is warp-private (one warp per ty)

        int cnt = 0;
        #pragma unroll
        for (int q = 0; q < 4; q++) {
            int x  = x0 + q * 32 + tx;
            int lx = q * 32 + tx + 4;
            bool pk = false;
            if (yok && x >= 1 && x <= W-2) {
                float c = dgs[t+1][ty+1][lx];
                if (c > THRESH) {
                    float m = fmaxf(fmaxf(svmax[ty][lx-1], svmax[ty][lx]),
                                    svmax[ty][lx+1]);
                    pk = (c >= m);
                }
            }
            unsigned wmask = __ballot_sync(0xFFFFFFFFu, pk);
            if (tx == 0) {
                d_maskw[(kt*H + y)*16 + (x0/32 + q)] = wmask;
                cnt += __popc(wmask);
            }
        }
        if (tx == 0) d_pcnt[(kt*H + y)*4 + blockIdx.x] = cnt;
        __syncwarp();   // done reading svmax before next test overwrites
    }
}

// ---------------------------------------------------------------
// Count+scan over 6656 rows from the small per-block count array.
// ---------------------------------------------------------------
__global__ void scan_k() {
    const int PER = (NROWS + 1023) / 1024;   // 7
    int tid = threadIdx.x;
    int vals[PER];
    int local = 0;
    int start = tid * PER;
    #pragma unroll
    for (int j = 0; j < PER; j++) {
        int idx = start + j;
        int v = 0;
        if (idx < NROWS) {
            int4 c = *(const int4*)(d_pcnt + idx*4);
            v = c.x + c.y + c.z + c.w;
        }
        vals[j] = v;
        local += v;
    }
    __shared__ int sh[1024];
    sh[tid] = local;
    __syncthreads();
    for (int off = 1; off < 1024; off <<= 1) {
        int v = (tid >= off) ? sh[tid - off] : 0;
        __syncthreads();
        sh[tid] += v;
        __syncthreads();
    }
    int run = sh[tid] - local;
    #pragma unroll
    for (int j = 0; j < PER; j++) {
        int idx = start + j;
        if (idx < NROWS) { d_rowcnt[idx] = run; run += vals[j]; }
    }
    if (tid == 1023) d_total = sh[1023];
}

// ---------------------------------------------------------------
// Fused fill + scatter (disjoint index ranges, order-independent).
// grid NROWS blocks of 32 threads.
// ---------------------------------------------------------------
__global__ void write_k(float* __restrict__ out) {
    int rid  = blockIdx.x;
    int lane = threadIdx.x;
    int total = d_total;
    float sig0 = d_sig[0];
    #pragma unroll
    for (int j = 0; j < 5; j++) {          // 5*NROWS = 33280 >= MAXPEAKS
        int f = rid + j * NROWS;
        if (f < MAXPEAKS && f >= total && lane < 3)
            out[3*f + lane] = (lane == 0) ? sig0 : 0.f;
    }
    int k = rid >> 9, y = rid & 511;
    int run = d_rowcnt[rid];
    float sg = d_sig[k];
    for (int w = 0; w < 16; w++) {
        unsigned word = d_maskw[rid*16 + w];
        if (word) {
            if ((word >> lane) & 1u) {
                int idx = run + __popc(word & ((1u << lane) - 1u));
                if (idx < MAXPEAKS) {
                    out[3*idx]     = sg;
                    out[3*idx + 1] = (float)y;
                    out[3*idx + 2] = (float)(w*32 + lane);
                }
            }
            run += __popc(word);
        }
    }
}

extern "C" void kernel_launch(void* const* d_in, const int* in_sizes, int n_in,
                              void* d_out, int out_size) {
    const float* x     = nullptr;
    const float* sigma = nullptr;
    for (int i = 0; i < n_in; i++) {
        if (in_sizes[i] == H * W)   x     = (const float*)d_in[i];
        else if (in_sizes[i] == NS) sigma = (const float*)d_in[i];
    }
    if (!x)     x     = (const float*)d_in[0];
    if (!sigma) sigma = (const float*)d_in[n_in - 1];

    float* out = (float*)d_out;                   // [32768, 3]

    build_kernels_k<<<NS, 128>>>(sigma);
    hblur_k<<<dim3(H, NS), 128>>>(x);
    vblur_k<<<dim3(W/VTX, H/VTY, NS), dim3(VTX, 16)>>>();
    peak_k<<<dim3(W/PTX, H/PTY, 6), dim3(32, 8)>>>();
    scan_k<<<1, 1024>>>();
    write_k<<<NROWS, 32>>>(out);
}